// round 2
// baseline (speedup 1.0000x reference)
#include <cuda_runtime.h>
#include <cuda_bf16.h>
#include <cstdint>

#define BS 16
#define SP_IN 512
#define SP_OUT 256
#define DN_IN 128
#define DN_OUT 128
#define N_STK 256
#define N_STK_PNT 32
#define N_BEF 512
#define C_COOR 128

// ---------------- scratch (device globals; no allocation allowed) ----------------
__device__ float g_coorT[BS * C_COOR * N_STK];        // [b][c][m]
__device__ float g_spT  [BS * N_STK * SP_IN];         // [b][m][c]
__device__ float g_wspT [SP_IN * SP_OUT];             // [c][o]
__device__ float g_normM[BS * N_STK];
__device__ float g_normB[BS * N_BEF];
__device__ int2   g_nn[BS * N_BEF];
__device__ float2 g_wt[BS * N_BEF];

// ---------------- helpers ----------------
__device__ __forceinline__ unsigned long long pack2(float a, float b) {
    unsigned long long r;
    asm("mov.b64 %0, {%1, %2};" : "=l"(r) : "f"(a), "f"(b));
    return r;
}
__device__ __forceinline__ float2 unpack2f(unsigned long long v) {
    float2 r;
    asm("mov.b64 {%0, %1}, %2;" : "=f"(r.x), "=f"(r.y) : "l"(v));
    return r;
}
// packed dual fp32 FMA: acc = a*b + acc (both lanes)
__device__ __forceinline__ void ffma2(unsigned long long &acc, unsigned long long a, unsigned long long b) {
    asm("fma.rn.f32x2 %0, %1, %2, %0;" : "+l"(acc) : "l"(a), "l"(b));
}
__device__ __forceinline__ unsigned mono(float f) {
    unsigned u = __float_as_uint(f);
    return (u & 0x80000000u) ? ~u : (u | 0x80000000u);
}
__device__ __forceinline__ float invmono(unsigned u) {
    unsigned v = (u & 0x80000000u) ? (u & 0x7FFFFFFFu) : ~u;
    return __uint_as_float(v);
}
// tanh-approx GELU (jax.nn.gelu default), NaN-safe for large |x|
__device__ __forceinline__ float gelu_tanh(float x) {
    float g = 0.7978845608028654f * x * fmaf(0.044715f, x * x, 1.0f);
    float e = __expf(2.0f * g);
    float th = 1.0f - 2.0f / (e + 1.0f);
    return 0.5f * x * (1.0f + th);
}
#define INV_SQRT_BN 0.99999500003749973f  // 1/sqrt(1+1e-5)

// ---------------- per-batch transpose [R,C] -> [C,R] ----------------
template<int R, int C, int WHICH>
__global__ void k_transpose(const float* __restrict__ src) {
    float* dstbase = (WHICH == 0) ? g_coorT : (WHICH == 1) ? g_spT : g_wspT;
    __shared__ float tile[32][33];
    int b = blockIdx.z;
    const float* s = src + (size_t)b * R * C;
    float* d = dstbase + (size_t)b * R * C;
    int r0 = blockIdx.y * 32, c0 = blockIdx.x * 32;
#pragma unroll
    for (int k = 0; k < 32; k += 8)
        tile[threadIdx.y + k][threadIdx.x] = s[(size_t)(r0 + threadIdx.y + k) * C + c0 + threadIdx.x];
    __syncthreads();
#pragma unroll
    for (int k = 0; k < 32; k += 8)
        d[(size_t)(c0 + threadIdx.y + k) * R + r0 + threadIdx.x] = tile[threadIdx.x][threadIdx.y + k];
}

// ---------------- row sum-of-squares (rows of 128 floats) ----------------
template<int WHICH>  // 0 -> g_normM, 1 -> g_normB
__global__ void k_norm128(const float* __restrict__ src, int rows) {
    float* dst = WHICH ? g_normB : g_normM;
    int warp = (blockIdx.x * blockDim.x + threadIdx.x) >> 5;
    int lane = threadIdx.x & 31;
    if (warp >= rows) return;
    float4 v = ((const float4*)(src + (size_t)warp * 128))[lane];
    float s = v.x * v.x + v.y * v.y + v.z * v.z + v.w * v.w;
#pragma unroll
    for (int off = 16; off; off >>= 1) s += __shfl_xor_sync(0xffffffffu, s, off);
    if (!lane) dst[warp] = s;
}

// ---------------- distances + top-2 + weights ----------------
__global__ __launch_bounds__(256) void k_topk(const float* __restrict__ bef) {
    __shared__ float befs[16 * 128];
    __shared__ unsigned long long red[8];
    __shared__ unsigned long long s_win;
    int n0 = blockIdx.x * 16, b = blockIdx.y;
    int tid = threadIdx.x;
    for (int idx = tid; idx < 16 * 128; idx += 256)
        befs[idx] = bef[((size_t)b * N_BEF + n0) * 128 + idx];
    __syncthreads();

    int m = tid;  // 256 threads == 256 candidate strokes
    float acc[16];
#pragma unroll
    for (int j = 0; j < 16; j++) acc[j] = 0.0f;
    const float* cT = g_coorT + (size_t)b * C_COOR * N_STK + m;
    for (int cb = 0; cb < 128; cb += 32) {          // chunked for lower rounding error
        float part[16];
#pragma unroll
        for (int j = 0; j < 16; j++) part[j] = 0.0f;
        for (int c0 = cb; c0 < cb + 32; c0 += 4) {
            float v0 = cT[(c0 + 0) * N_STK];
            float v1 = cT[(c0 + 1) * N_STK];
            float v2 = cT[(c0 + 2) * N_STK];
            float v3 = cT[(c0 + 3) * N_STK];
#pragma unroll
            for (int j = 0; j < 16; j++) {
                float4 bf = *(const float4*)&befs[j * 128 + c0];
                part[j] = fmaf(bf.x, v0, part[j]);
                part[j] = fmaf(bf.y, v1, part[j]);
                part[j] = fmaf(bf.z, v2, part[j]);
                part[j] = fmaf(bf.w, v3, part[j]);
            }
        }
#pragma unroll
        for (int j = 0; j < 16; j++) acc[j] += part[j];
    }
    float nm = g_normM[b * N_STK + m];
    int lane = tid & 31, wid = tid >> 5;
    for (int j = 0; j < 16; j++) {
        float d2v = g_normB[b * N_BEF + n0 + j] + nm - 2.0f * acc[j];
        unsigned long long key = ((unsigned long long)mono(d2v) << 8) | (unsigned)m;
        unsigned long long k = key;
#pragma unroll
        for (int off = 16; off; off >>= 1) {
            unsigned long long o = __shfl_xor_sync(0xffffffffu, k, off);
            if (o < k) k = o;
        }
        if (lane == 0) red[wid] = k;
        __syncthreads();
        if (tid == 0) {
            unsigned long long mn = red[0];
#pragma unroll
            for (int w = 1; w < 8; w++) if (red[w] < mn) mn = red[w];
            s_win = mn;
        }
        __syncthreads();
        unsigned long long win1 = s_win;
        k = (key == win1) ? 0xFFFFFFFFFFFFFFFFull : key;
#pragma unroll
        for (int off = 16; off; off >>= 1) {
            unsigned long long o = __shfl_xor_sync(0xffffffffu, k, off);
            if (o < k) k = o;
        }
        if (lane == 0) red[wid] = k;
        __syncthreads();
        if (tid == 0) {
            unsigned long long mn2 = red[0];
#pragma unroll
            for (int w = 1; w < 8; w++) if (red[w] < mn2) mn2 = red[w];
            float d0 = invmono((unsigned)(win1 >> 8));
            float d1 = invmono((unsigned)(mn2 >> 8));
            int i0 = (int)(win1 & 0xFF), i1 = (int)(mn2 & 0xFF);
            float r0 = 1.0f / (d0 + 1e-8f), r1 = 1.0f / (d1 + 1e-8f);
            float s = r0 + r1;
            g_nn[b * N_BEF + n0 + j] = make_int2(i0, i1);
            g_wt[b * N_BEF + n0 + j] = make_float2(r0 / s, r1 / s);
        }
        __syncthreads();
    }
}

// ---------------- sparse branch: gather+interp, GEMM, BN+GELU ----------------
__global__ __launch_bounds__(256) void k_sparse(const float* __restrict__ b_sp,
                                                const float* __restrict__ gam,
                                                const float* __restrict__ bet,
                                                float* __restrict__ out) {
    __shared__ float V[512 * 20];   // [c][j], stride 20 (16B-aligned rows)
    __shared__ int2 ii[16];
    __shared__ float2 ww[16];
    int n0 = blockIdx.x * 16, b = blockIdx.y, tid = threadIdx.x;
    if (tid < 16) {
        ii[tid] = g_nn[b * N_BEF + n0 + tid];
        ww[tid] = g_wt[b * N_BEF + n0 + tid];
    }
    __syncthreads();
    const float* sT = g_spT + (size_t)b * N_STK * SP_IN;
    for (int idx = tid; idx < 512 * 16; idx += 256) {
        int j = idx >> 9, c = idx & 511;
        int2 id = ii[j];
        float2 wt = ww[j];
        V[c * 20 + j] = wt.x * sT[(size_t)id.x * SP_IN + c] + wt.y * sT[(size_t)id.y * SP_IN + c];
    }
    __syncthreads();
    int o = tid;
    unsigned long long acc[8] = {0, 0, 0, 0, 0, 0, 0, 0};
#pragma unroll 4
    for (int c = 0; c < 512; c++) {
        float wv = g_wspT[c * SP_OUT + o];
        unsigned long long w2 = pack2(wv, wv);
        const ulonglong2* vr = (const ulonglong2*)&V[c * 20];
        ulonglong2 p0 = vr[0], p1 = vr[1], p2 = vr[2], p3 = vr[3];
        ffma2(acc[0], w2, p0.x); ffma2(acc[1], w2, p0.y);
        ffma2(acc[2], w2, p1.x); ffma2(acc[3], w2, p1.y);
        ffma2(acc[4], w2, p2.x); ffma2(acc[5], w2, p2.y);
        ffma2(acc[6], w2, p3.x); ffma2(acc[7], w2, p3.y);
    }
    float bias = b_sp[o];
    float sc = gam[o] * INV_SQRT_BN;
    float bt = bet[o];
    float res[16];
#pragma unroll
    for (int p = 0; p < 8; p++) {
        float2 f = unpack2f(acc[p]);
        res[2 * p]     = gelu_tanh(fmaf(f.x + bias, sc, bt));
        res[2 * p + 1] = gelu_tanh(fmaf(f.y + bias, sc, bt));
    }
    float* ob = out + ((size_t)b * SP_OUT + o) * N_BEF + n0;
#pragma unroll
    for (int q = 0; q < 4; q++)
        *(float4*)&ob[4 * q] = make_float4(res[4 * q], res[4 * q + 1], res[4 * q + 2], res[4 * q + 3]);
}

// ---------------- dense branch: interp + ConvT(k4,s2,p3) + BN + GELU ----------------
// T[c][l] (l=0..33) holds Dflat[b,c, clamp(32n-1+l, 0, 16383)].
// out[2L]   = sum_c W3*T[L]   + W1*T[L+1]
// out[2L+1] = sum_c W2*T[L+1] + W0*T[L+2],  L in 0..31 local, tap k = w_ct[c][o][k]
__global__ __launch_bounds__(256, 2) void k_dense(const float* __restrict__ dense,
                                                  const float* __restrict__ w_ct,
                                                  const float* __restrict__ b_ct,
                                                  const float* __restrict__ gam,
                                                  const float* __restrict__ bet,
                                                  float* __restrict__ out) {
    __shared__ float sm[128 * 36];  // row stride 36 floats (cols 0..33 valid)
    int n = blockIdx.x, b = blockIdx.y, tid = threadIdx.x;
    int base = b * N_BEF;
    int2 iM = g_nn[base + n];
    float2 wM = g_wt[base + n];
    const float* dB = dense + (size_t)b * DN_IN * N_STK * N_STK_PNT;

    // phase 1: interpolated tile
    {
        int warp = tid >> 5, p = tid & 31;
        for (int c = warp; c < 128; c += 8) {
            float v0 = dB[((size_t)c * N_STK + iM.x) * N_STK_PNT + p];
            float v1 = dB[((size_t)c * N_STK + iM.y) * N_STK_PNT + p];
            sm[c * 36 + 1 + p] = wM.x * v0 + wM.y * v1;
        }
    }
    if (tid < 128) {
        int c = tid;
        int jl = 32 * n - 1; if (jl < 0) jl = 0;
        int sL = jl >> 5, pL = jl & 31;
        int2 iL = g_nn[base + sL]; float2 wL = g_wt[base + sL];
        sm[c * 36] = wL.x * dB[((size_t)c * N_STK + iL.x) * N_STK_PNT + pL]
                   + wL.y * dB[((size_t)c * N_STK + iL.y) * N_STK_PNT + pL];
        int jr = 32 * n + 32; if (jr > 16383) jr = 16383;
        int sR = jr >> 5, pR = jr & 31;
        int2 iR = g_nn[base + sR]; float2 wR = g_wt[base + sR];
        sm[c * 36 + 33] = wR.x * dB[((size_t)c * N_STK + iR.x) * N_STK_PNT + pR]
                        + wR.y * dB[((size_t)c * N_STK + iR.y) * N_STK_PNT + pR];
    }
    __syncthreads();

    // phase 2: per-tap partial sums S_k over pair-packed columns (f32x2 FMAs)
    int o = tid & 127, h = tid >> 7, r0 = h << 4;
    unsigned long long a3[8], a1[9], a2[9], a0[8];
#pragma unroll
    for (int p = 0; p < 8; p++) { a3[p] = 0ull; a0[p] = 0ull; }
#pragma unroll
    for (int p = 0; p < 9; p++) { a1[p] = 0ull; a2[p] = 0ull; }
    const float4* w4 = (const float4*)w_ct;  // [c][o] -> 4 taps
#pragma unroll 2
    for (int c = 0; c < 128; c++) {
        float4 w = w4[c * 128 + o];
        unsigned long long w0p = pack2(w.x, w.x);
        unsigned long long w1p = pack2(w.y, w.y);
        unsigned long long w2p = pack2(w.z, w.z);
        unsigned long long w3p = pack2(w.w, w.w);
        const ulonglong2* dr = (const ulonglong2*)&sm[c * 36 + r0];
        ulonglong2 q0 = dr[0], q1 = dr[1], q2 = dr[2], q3 = dr[3], q4 = dr[4];
        unsigned long long d0 = q0.x, d1 = q0.y, d2 = q1.x, d3 = q1.y, d4 = q2.x;
        unsigned long long d5 = q2.y, d6 = q3.x, d7 = q3.y, d8 = q4.x;
        ffma2(a3[0], w3p, d0); ffma2(a3[1], w3p, d1); ffma2(a3[2], w3p, d2); ffma2(a3[3], w3p, d3);
        ffma2(a3[4], w3p, d4); ffma2(a3[5], w3p, d5); ffma2(a3[6], w3p, d6); ffma2(a3[7], w3p, d7);
        ffma2(a1[0], w1p, d0); ffma2(a1[1], w1p, d1); ffma2(a1[2], w1p, d2); ffma2(a1[3], w1p, d3);
        ffma2(a1[4], w1p, d4); ffma2(a1[5], w1p, d5); ffma2(a1[6], w1p, d6); ffma2(a1[7], w1p, d7);
        ffma2(a1[8], w1p, d8);
        ffma2(a2[0], w2p, d0); ffma2(a2[1], w2p, d1); ffma2(a2[2], w2p, d2); ffma2(a2[3], w2p, d3);
        ffma2(a2[4], w2p, d4); ffma2(a2[5], w2p, d5); ffma2(a2[6], w2p, d6); ffma2(a2[7], w2p, d7);
        ffma2(a2[8], w2p, d8);
        ffma2(a0[0], w0p, d1); ffma2(a0[1], w0p, d2); ffma2(a0[2], w0p, d3); ffma2(a0[3], w0p, d4);
        ffma2(a0[4], w0p, d5); ffma2(a0[5], w0p, d6); ffma2(a0[6], w0p, d7); ffma2(a0[7], w0p, d8);
    }

    // epilogue: combine taps, bias + BN + GELU, store
    float A3f[16], A1f[18], A2f[18], A0f[18];
#pragma unroll
    for (int p = 0; p < 8; p++) { float2 f = unpack2f(a3[p]); A3f[2 * p] = f.x; A3f[2 * p + 1] = f.y; }
#pragma unroll
    for (int p = 0; p < 9; p++) { float2 f = unpack2f(a1[p]); A1f[2 * p] = f.x; A1f[2 * p + 1] = f.y; }
#pragma unroll
    for (int p = 0; p < 9; p++) { float2 f = unpack2f(a2[p]); A2f[2 * p] = f.x; A2f[2 * p + 1] = f.y; }
#pragma unroll
    for (int p = 0; p < 8; p++) { float2 f = unpack2f(a0[p]); A0f[2 * p + 2] = f.x; A0f[2 * p + 3] = f.y; }
    float bias = b_ct[o];
    float sc = gam[o] * INV_SQRT_BN;
    float bt = bet[o];
    float res[32];
#pragma unroll
    for (int i = 0; i < 16; i++) {
        float e  = A3f[i] + A1f[i + 1];
        float od = A2f[i + 1] + A0f[i + 2];
        res[2 * i]     = gelu_tanh(fmaf(e + bias, sc, bt));
        res[2 * i + 1] = gelu_tanh(fmaf(od + bias, sc, bt));
    }
    float* ob = out + (((size_t)b * DN_OUT + o) * N_BEF + n) * 64 + 32 * h;
#pragma unroll
    for (int q = 0; q < 8; q++)
        *(float4*)&ob[4 * q] = make_float4(res[4 * q], res[4 * q + 1], res[4 * q + 2], res[4 * q + 3]);
}

// ---------------- launcher ----------------
extern "C" void kernel_launch(void* const* d_in, const int* in_sizes, int n_in,
                              void* d_out, int out_size) {
    const float* sparse_fea = (const float*)d_in[0];
    const float* dense_fea  = (const float*)d_in[1];
    const float* stk_coor   = (const float*)d_in[2];
    const float* stk_bef    = (const float*)d_in[3];
    const float* w_sp   = (const float*)d_in[4];
    const float* b_sp   = (const float*)d_in[5];
    const float* gam_sp = (const float*)d_in[6];
    const float* bet_sp = (const float*)d_in[7];
    const float* w_ct   = (const float*)d_in[8];
    const float* b_ct   = (const float*)d_in[9];
    const float* gam_dn = (const float*)d_in[10];
    const float* bet_dn = (const float*)d_in[11];
    float* out_sp = (float*)d_out;
    float* out_dn = out_sp + (size_t)BS * SP_OUT * N_BEF;

    k_transpose<256, 128, 0><<<dim3(4, 8, 16), dim3(32, 8)>>>(stk_coor);
    k_transpose<512, 256, 1><<<dim3(8, 16, 16), dim3(32, 8)>>>(sparse_fea);
    k_transpose<256, 512, 2><<<dim3(16, 8, 1), dim3(32, 8)>>>(w_sp);
    k_norm128<0><<<512, 256>>>(stk_coor, BS * N_STK);
    k_norm128<1><<<1024, 256>>>(stk_bef, BS * N_BEF);
    k_topk<<<dim3(32, 16), 256>>>(stk_bef);
    k_sparse<<<dim3(32, 16), 256>>>(b_sp, gam_sp, bet_sp, out_sp);
    k_dense<<<dim3(512, 16), 256>>>(dense_fea, w_ct, b_ct, gam_dn, bet_dn, out_dn);
}